// round 8
// baseline (speedup 1.0000x reference)
#include <cuda_runtime.h>
#include <cstddef>
#include <cstdint>

// mRoPE, 256-bit global accesses, 2 chunks/thread, front-batched loads.
// q[T, 32*128], k[T, 8*128], cos/sin[3, T, 64]; half = 64.
// sections (32,32,32): j<32 -> plane 0, j in [32,64) -> plane 1.
// out[j]    = x[j]*c[j]   - x[j+64]*s[j]
// out[j+64] = x[j+64]*c[j] + x[j]*s[j]
//
// Chunk = 8 consecutive floats of a head's first half + matching 8 of the
// second half: 4x v8 loads (128B), 2x v8 stores (64B). Two chunks per thread.

#define T_TOK 16384
#define HALF  64
#define NQH   32
#define NKH   8
#define HS    128

#define Q_CHUNKS (T_TOK * NQH * (HALF / 8))   // 4,194,304
#define K_CHUNKS (T_TOK * NKH * (HALF / 8))   // 1,048,576
#define CPB      512                           // chunks per block (2/thread)
#define Q_BLOCKS (Q_CHUNKS / CPB)              // 8192
#define K_BLOCKS (K_CHUNKS / CPB)              // 2048

struct V8 { uint32_t r[8]; };

__device__ __forceinline__ V8 ldg256(const float* p)
{
    V8 v;
    asm volatile("ld.global.nc.v8.b32 {%0,%1,%2,%3,%4,%5,%6,%7}, [%8];"
                 : "=r"(v.r[0]), "=r"(v.r[1]), "=r"(v.r[2]), "=r"(v.r[3]),
                   "=r"(v.r[4]), "=r"(v.r[5]), "=r"(v.r[6]), "=r"(v.r[7])
                 : "l"(p));
    return v;
}

__device__ __forceinline__ void stg256(float* p, const V8& v)
{
    asm volatile("st.global.v8.b32 [%0], {%1,%2,%3,%4,%5,%6,%7,%8};"
                 :: "l"(p),
                    "r"(v.r[0]), "r"(v.r[1]), "r"(v.r[2]), "r"(v.r[3]),
                    "r"(v.r[4]), "r"(v.r[5]), "r"(v.r[6]), "r"(v.r[7])
                 : "memory");
}

__device__ __forceinline__ void rope_math_v8(const V8& a, const V8& b,
                                             const V8& c, const V8& s,
                                             V8& o1, V8& o2)
{
#pragma unroll
    for (int e = 0; e < 8; e++) {
        const float af = __uint_as_float(a.r[e]);
        const float bf = __uint_as_float(b.r[e]);
        const float cf = __uint_as_float(c.r[e]);
        const float sf = __uint_as_float(s.r[e]);
        o1.r[e] = __float_as_uint(fmaf(af, cf, -bf * sf));
        o2.r[e] = __float_as_uint(fmaf(bf, cf,  af * sf));
    }
}

struct ChunkAddr { size_t off; size_t cs_off; };

__device__ __forceinline__ ChunkAddr decode_q(int i)
{
    const int t  = i >> 8;             // 256 chunks/token
    const int r  = i & 255;
    const int j8 = r & 7;
    ChunkAddr u;
    u.off    = ((size_t)t << 12) + ((size_t)(r >> 3) << 7) + (j8 << 3);
    u.cs_off = (size_t)(j8 >> 2) * (T_TOK * HALF) + ((size_t)t << 6) + (j8 << 3);
    return u;
}

__device__ __forceinline__ ChunkAddr decode_k(int i)
{
    const int t  = i >> 6;             // 64 chunks/token
    const int r  = i & 63;
    const int j8 = r & 7;
    ChunkAddr u;
    u.off    = ((size_t)t << 10) + ((size_t)(r >> 3) << 7) + (j8 << 3);
    u.cs_off = (size_t)(j8 >> 2) * (T_TOK * HALF) + ((size_t)t << 6) + (j8 << 3);
    return u;
}

__device__ __forceinline__ void rope_2chunk(const float* __restrict__ src,
                                            float* __restrict__ dst,
                                            const float* __restrict__ cosp,
                                            const float* __restrict__ sinp,
                                            ChunkAddr u0, ChunkAddr u1)
{
    // Front-batch: both chunks' q/k data + chunk0 cos/sin (6 independent
    // 32B loads in flight), chunk1 cos/sin right behind.
    const V8 a0 = ldg256(src + u0.off);
    const V8 b0 = ldg256(src + u0.off + HALF);
    const V8 a1 = ldg256(src + u1.off);
    const V8 b1 = ldg256(src + u1.off + HALF);
    const V8 c0 = ldg256(cosp + u0.cs_off);
    const V8 s0 = ldg256(sinp + u0.cs_off);

    V8 o1, o2;
    rope_math_v8(a0, b0, c0, s0, o1, o2);
    stg256(dst + u0.off,        o1);
    stg256(dst + u0.off + HALF, o2);

    const V8 c1 = ldg256(cosp + u1.cs_off);
    const V8 s1 = ldg256(sinp + u1.cs_off);
    rope_math_v8(a1, b1, c1, s1, o1, o2);
    stg256(dst + u1.off,        o1);
    stg256(dst + u1.off + HALF, o2);
}

__global__ __launch_bounds__(256)
void mrope_v8x2_kernel(const float* __restrict__ q,
                       const float* __restrict__ k,
                       const float* __restrict__ cosp,
                       const float* __restrict__ sinp,
                       float* __restrict__ qo,
                       float* __restrict__ ko)
{
    const int bid = blockIdx.x;
    const int tid = threadIdx.x;

    if (bid < Q_BLOCKS) {
        const int base = bid * CPB;
        rope_2chunk(q, qo, cosp, sinp,
                    decode_q(base + tid), decode_q(base + 256 + tid));
    } else {
        const int base = (bid - Q_BLOCKS) * CPB;
        rope_2chunk(k, ko, cosp, sinp,
                    decode_k(base + tid), decode_k(base + 256 + tid));
    }
}

extern "C" void kernel_launch(void* const* d_in, const int* in_sizes, int n_in,
                              void* d_out, int out_size)
{
    const float* q    = (const float*)d_in[0];
    const float* k    = (const float*)d_in[1];
    const float* cosp = (const float*)d_in[2];
    const float* sinp = (const float*)d_in[3];

    float* qo = (float*)d_out;
    float* ko = qo + (size_t)T_TOK * NQH * HS;

    mrope_v8x2_kernel<<<Q_BLOCKS + K_BLOCKS, 256>>>(q, k, cosp, sinp, qo, ko);
}

// round 9
// speedup vs baseline: 1.0034x; 1.0034x over previous
#include <cuda_runtime.h>
#include <cstddef>
#include <cstdint>

// mRoPE flat elementwise with 256-bit global accesses (sm_103a LDG.E.256).
// Best-known shape (R7) + cache hints: evict-first loads for touch-once q/k,
// .cs stores for prompt L2 writeback in graph-replay steady state.
// q[T, 32*128], k[T, 8*128], cos/sin[3, T, 64]; half = 64.
// sections (32,32,32): j<32 -> plane 0, j in [32,64) -> plane 1.
// out[j]    = x[j]*c[j]   - x[j+64]*s[j]
// out[j+64] = x[j+64]*c[j] + x[j]*s[j]

#define T_TOK 16384
#define HALF  64
#define NQH   32
#define NKH   8
#define HS    128

#define Q_CHUNKS (T_TOK * NQH * (HALF / 8))   // 4,194,304
#define K_CHUNKS (T_TOK * NKH * (HALF / 8))   // 1,048,576
#define Q_BLOCKS (Q_CHUNKS / 256)             // 16384
#define K_BLOCKS (K_CHUNKS / 256)             // 4096

struct V8 { uint32_t r[8]; };

// Touch-once stream load: don't let it displace cos/sin in L1.
__device__ __forceinline__ V8 ldg256_stream(const float* p)
{
    V8 v;
    asm volatile("ld.global.nc.L1::evict_first.v8.b32 {%0,%1,%2,%3,%4,%5,%6,%7}, [%8];"
                 : "=r"(v.r[0]), "=r"(v.r[1]), "=r"(v.r[2]), "=r"(v.r[3]),
                   "=r"(v.r[4]), "=r"(v.r[5]), "=r"(v.r[6]), "=r"(v.r[7])
                 : "l"(p));
    return v;
}

// Reused cos/sin load: normal caching.
__device__ __forceinline__ V8 ldg256(const float* p)
{
    V8 v;
    asm volatile("ld.global.nc.v8.b32 {%0,%1,%2,%3,%4,%5,%6,%7}, [%8];"
                 : "=r"(v.r[0]), "=r"(v.r[1]), "=r"(v.r[2]), "=r"(v.r[3]),
                   "=r"(v.r[4]), "=r"(v.r[5]), "=r"(v.r[6]), "=r"(v.r[7])
                 : "l"(p));
    return v;
}

// Streaming store: evict-first so dirty lines drain during the kernel,
// not as a tail into the next replay.
__device__ __forceinline__ void stg256_cs(float* p, const V8& v)
{
    asm volatile("st.global.cs.v8.b32 [%0], {%1,%2,%3,%4,%5,%6,%7,%8};"
                 :: "l"(p),
                    "r"(v.r[0]), "r"(v.r[1]), "r"(v.r[2]), "r"(v.r[3]),
                    "r"(v.r[4]), "r"(v.r[5]), "r"(v.r[6]), "r"(v.r[7])
                 : "memory");
}

__device__ __forceinline__ void rope_chunk(const float* __restrict__ src,
                                           float* __restrict__ dst,
                                           const float* __restrict__ cosp,
                                           const float* __restrict__ sinp,
                                           size_t off, size_t cs_off)
{
    const V8 a = ldg256_stream(src + off);          // x1
    const V8 b = ldg256_stream(src + off + HALF);   // x2
    const V8 c = ldg256(cosp + cs_off);
    const V8 s = ldg256(sinp + cs_off);

    V8 o1, o2;
#pragma unroll
    for (int e = 0; e < 8; e++) {
        const float af = __uint_as_float(a.r[e]);
        const float bf = __uint_as_float(b.r[e]);
        const float cf = __uint_as_float(c.r[e]);
        const float sf = __uint_as_float(s.r[e]);
        o1.r[e] = __float_as_uint(fmaf(af, cf, -bf * sf));
        o2.r[e] = __float_as_uint(fmaf(bf, cf,  af * sf));
    }

    stg256_cs(dst + off,        o1);
    stg256_cs(dst + off + HALF, o2);
}

__global__ __launch_bounds__(256)
void mrope_v8cs_kernel(const float* __restrict__ q,
                       const float* __restrict__ k,
                       const float* __restrict__ cosp,
                       const float* __restrict__ sinp,
                       float* __restrict__ qo,
                       float* __restrict__ ko)
{
    const int bid = blockIdx.x;
    const int tid = threadIdx.x;

    if (bid < Q_BLOCKS) {
        const int i  = (bid << 8) + tid;   // q chunk index
        const int t  = i >> 8;             // 256 chunks/token
        const int r  = i & 255;
        const int j8 = r & 7;              // chunk within half (0..7)
        const size_t off    = ((size_t)t << 12) + ((size_t)(r >> 3) << 7) + (j8 << 3);
        const size_t cs_off = (size_t)(j8 >> 2) * (T_TOK * HALF) + ((size_t)t << 6) + (j8 << 3);
        rope_chunk(q, qo, cosp, sinp, off, cs_off);
    } else {
        const int i  = ((bid - Q_BLOCKS) << 8) + tid;  // k chunk index
        const int t  = i >> 6;             // 64 chunks/token
        const int r  = i & 63;
        const int j8 = r & 7;
        const size_t off    = ((size_t)t << 10) + ((size_t)(r >> 3) << 7) + (j8 << 3);
        const size_t cs_off = (size_t)(j8 >> 2) * (T_TOK * HALF) + ((size_t)t << 6) + (j8 << 3);
        rope_chunk(k, ko, cosp, sinp, off, cs_off);
    }
}

extern "C" void kernel_launch(void* const* d_in, const int* in_sizes, int n_in,
                              void* d_out, int out_size)
{
    const float* q    = (const float*)d_in[0];
    const float* k    = (const float*)d_in[1];
    const float* cosp = (const float*)d_in[2];
    const float* sinp = (const float*)d_in[3];

    float* qo = (float*)d_out;
    float* ko = qo + (size_t)T_TOK * NQH * HS;

    mrope_v8cs_kernel<<<Q_BLOCKS + K_BLOCKS, 256>>>(q, k, cosp, sinp, qo, ko);
}

// round 10
// speedup vs baseline: 1.0245x; 1.0210x over previous
#include <cuda_runtime.h>
#include <cstddef>
#include <cstdint>

// mRoPE, 256-bit global accesses (sm_103a), R7 shape + L2 residency policy:
//   q/k stream + stores -> L2::evict_first (don't thrash L2)
//   cos/sin             -> L2::evict_last  (pin ~17MB table across graph replays)
// q[T, 32*128], k[T, 8*128], cos/sin[3, T, 64]; half = 64.
// sections (32,32,32): j<32 -> plane 0, j in [32,64) -> plane 1.
// out[j]    = x[j]*c[j]   - x[j+64]*s[j]
// out[j+64] = x[j+64]*c[j] + x[j]*s[j]

#define T_TOK 16384
#define HALF  64
#define NQH   32
#define NKH   8
#define HS    128

#define Q_CHUNKS (T_TOK * NQH * (HALF / 8))   // 4,194,304
#define K_CHUNKS (T_TOK * NKH * (HALF / 8))   // 1,048,576
#define Q_BLOCKS (Q_CHUNKS / 256)             // 16384
#define K_BLOCKS (K_CHUNKS / 256)             // 4096

struct V8 { uint32_t r[8]; };

__device__ __forceinline__ uint64_t make_policy_evict_first()
{
    uint64_t pol;
    asm("createpolicy.fractional.L2::evict_first.b64 %0, 1.0;" : "=l"(pol));
    return pol;
}

__device__ __forceinline__ uint64_t make_policy_evict_last()
{
    uint64_t pol;
    asm("createpolicy.fractional.L2::evict_last.b64 %0, 1.0;" : "=l"(pol));
    return pol;
}

// Touch-once stream load: L2 evict-first.
__device__ __forceinline__ V8 ldg256_stream(const float* p, uint64_t pol)
{
    V8 v;
    asm volatile("ld.global.nc.L2::cache_hint.v8.b32 {%0,%1,%2,%3,%4,%5,%6,%7}, [%8], %9;"
                 : "=r"(v.r[0]), "=r"(v.r[1]), "=r"(v.r[2]), "=r"(v.r[3]),
                   "=r"(v.r[4]), "=r"(v.r[5]), "=r"(v.r[6]), "=r"(v.r[7])
                 : "l"(p), "l"(pol));
    return v;
}

// Reused cos/sin load: L2 evict-last (pin across replays).
__device__ __forceinline__ V8 ldg256_pin(const float* p, uint64_t pol)
{
    V8 v;
    asm volatile("ld.global.nc.L2::cache_hint.v8.b32 {%0,%1,%2,%3,%4,%5,%6,%7}, [%8], %9;"
                 : "=r"(v.r[0]), "=r"(v.r[1]), "=r"(v.r[2]), "=r"(v.r[3]),
                   "=r"(v.r[4]), "=r"(v.r[5]), "=r"(v.r[6]), "=r"(v.r[7])
                 : "l"(p), "l"(pol));
    return v;
}

// Stream store: L2 evict-first (writeback path, don't displace cos/sin).
__device__ __forceinline__ void stg256(float* p, const V8& v, uint64_t pol)
{
    asm volatile("st.global.L2::cache_hint.v8.b32 [%0], {%1,%2,%3,%4,%5,%6,%7,%8}, %9;"
                 :: "l"(p),
                    "r"(v.r[0]), "r"(v.r[1]), "r"(v.r[2]), "r"(v.r[3]),
                    "r"(v.r[4]), "r"(v.r[5]), "r"(v.r[6]), "r"(v.r[7]),
                    "l"(pol)
                 : "memory");
}

__device__ __forceinline__ void rope_chunk(const float* __restrict__ src,
                                           float* __restrict__ dst,
                                           const float* __restrict__ cosp,
                                           const float* __restrict__ sinp,
                                           size_t off, size_t cs_off,
                                           uint64_t pol_stream, uint64_t pol_pin)
{
    const V8 a = ldg256_stream(src + off,        pol_stream);  // x1
    const V8 b = ldg256_stream(src + off + HALF, pol_stream);  // x2
    const V8 c = ldg256_pin(cosp + cs_off, pol_pin);
    const V8 s = ldg256_pin(sinp + cs_off, pol_pin);

    V8 o1, o2;
#pragma unroll
    for (int e = 0; e < 8; e++) {
        const float af = __uint_as_float(a.r[e]);
        const float bf = __uint_as_float(b.r[e]);
        const float cf = __uint_as_float(c.r[e]);
        const float sf = __uint_as_float(s.r[e]);
        o1.r[e] = __float_as_uint(fmaf(af, cf, -bf * sf));
        o2.r[e] = __float_as_uint(fmaf(bf, cf,  af * sf));
    }

    stg256(dst + off,        o1, pol_stream);
    stg256(dst + off + HALF, o2, pol_stream);
}

__global__ __launch_bounds__(256)
void mrope_v8l2_kernel(const float* __restrict__ q,
                       const float* __restrict__ k,
                       const float* __restrict__ cosp,
                       const float* __restrict__ sinp,
                       float* __restrict__ qo,
                       float* __restrict__ ko)
{
    const int bid = blockIdx.x;
    const int tid = threadIdx.x;

    const uint64_t pol_stream = make_policy_evict_first();
    const uint64_t pol_pin    = make_policy_evict_last();

    if (bid < Q_BLOCKS) {
        const int i  = (bid << 8) + tid;   // q chunk index
        const int t  = i >> 8;             // 256 chunks/token
        const int r  = i & 255;
        const int j8 = r & 7;              // chunk within half (0..7)
        const size_t off    = ((size_t)t << 12) + ((size_t)(r >> 3) << 7) + (j8 << 3);
        const size_t cs_off = (size_t)(j8 >> 2) * (T_TOK * HALF) + ((size_t)t << 6) + (j8 << 3);
        rope_chunk(q, qo, cosp, sinp, off, cs_off, pol_stream, pol_pin);
    } else {
        const int i  = ((bid - Q_BLOCKS) << 8) + tid;  // k chunk index
        const int t  = i >> 6;             // 64 chunks/token
        const int r  = i & 63;
        const int j8 = r & 7;
        const size_t off    = ((size_t)t << 10) + ((size_t)(r >> 3) << 7) + (j8 << 3);
        const size_t cs_off = (size_t)(j8 >> 2) * (T_TOK * HALF) + ((size_t)t << 6) + (j8 << 3);
        rope_chunk(k, ko, cosp, sinp, off, cs_off, pol_stream, pol_pin);
    }
}

extern "C" void kernel_launch(void* const* d_in, const int* in_sizes, int n_in,
                              void* d_out, int out_size)
{
    const float* q    = (const float*)d_in[0];
    const float* k    = (const float*)d_in[1];
    const float* cosp = (const float*)d_in[2];
    const float* sinp = (const float*)d_in[3];

    float* qo = (float*)d_out;
    float* ko = qo + (size_t)T_TOK * NQH * HS;

    mrope_v8l2_kernel<<<Q_BLOCKS + K_BLOCKS, 256>>>(q, k, cosp, sinp, qo, ko);
}